// round 15
// baseline (speedup 1.0000x reference)
#include <cuda_runtime.h>

#define HH 384
#define WW 384
#define NBATCH 16
#define GROUPS 5
#define ICG 4
#define OCG 8
#define KS 5
#define PAD 2
#define TILE 32
#define HALO 36
#define SINX 38   // s_in x-stride (even -> u64-aligned rows), 4*36*38*4 = 21888 B
#define SHX 40    // s_h x-stride (mult of 4 -> STS.128-aligned), 2*3*36*40*4 = 34560 B

typedef unsigned long long u64;

// Dup-packed (v,v) 1D Gaussian-derivative filters: [group][deriv 0..2][tap 0..4]
__device__ u64 g_d2[GROUPS][3][KS];

// ---------------------------------------------------------------------------
__global__ void make_filters_kernel(const float* __restrict__ scales) {
    int s = threadIdx.x;
    if (s >= GROUPS) return;
    const int FS_[5] = {1, 1, 1, 2, 2};
    float mn = 0.2f * s, mx = mn + 0.2f;
    float sigma = (mx - mn) * 0.5f * tanhf(scales[s]) + (mn + mx) * 0.5f;
    int fs = FS_[s], len = 2 * fs + 1;

    float g[5]; float gsum = 0.f;
    for (int k = 0; k < len; k++) {
        float x = (float)(k - fs);
        g[k] = expf(-(x * x) / (2.f * sigma * sigma));
        gsum += g[k];
    }
    float inv = 1.f / gsum;
    const float SQRT2 = 1.4142135623730951f;
    float c1 = -1.f / (sigma * SQRT2);

    float d[3][5];
    for (int i = 0; i < 3; i++)
        for (int k = 0; k < 5; k++) d[i][k] = 0.f;
    int p = (KS - len) / 2;
    for (int k = 0; k < len; k++) {
        float x = (float)(k - fs);
        float u = x / (sigma * SQRT2);
        float gg = g[k] * inv;
        d[0][p + k] = gg;
        d[1][p + k] = c1 * (2.f * u) * gg;
        d[2][p + k] = c1 * c1 * (4.f * u * u - 2.f) * gg;
    }
    for (int i = 0; i < 3; i++)
        for (int k = 0; k < 5; k++) {
            unsigned ui = __float_as_uint(d[i][k]);
            g_d2[s][i][k] = ((u64)ui << 32) | ui;
        }
}

// ---------------------------------------------------------------------------
__device__ __forceinline__ u64 fma2(u64 a, u64 b, u64 c) {
    u64 d;
    asm("fma.rn.f32x2 %0, %1, %2, %3;" : "=l"(d) : "l"(a), "l"(b), "l"(c));
    return d;
}
__device__ __forceinline__ u64 pk2f(float a, float b) {
    u64 r;
    asm("mov.b64 %0, {%1, %2};" : "=l"(r)
        : "r"(__float_as_uint(a)), "r"(__float_as_uint(b)));
    return r;
}
__device__ __forceinline__ u64 dup2(float a) {
    u64 r;
    asm("mov.b64 %0, {%1, %1};" : "=l"(r) : "r"(__float_as_uint(a)));
    return r;
}
__device__ __forceinline__ float2 uview(u64 v) {
    float2 f;
    asm("mov.b64 {%0, %1}, %2;" : "=f"(f.x), "=f"(f.y) : "l"(v));
    return f;
}

// ---------------------------------------------------------------------------
// Fused separable conv (R3 structure, squeezed for 4 CTAs/SM):
//   stage 1 (coop):  s_h[j][y][x] = d_j *_x s_in   (per 2-ic batch)
//   stage 2 (thread): vertical d_i *_y s_h[j] + pointwise alpha mix
// ---------------------------------------------------------------------------
__global__ __launch_bounds__(256, 4)
void conv_kernel(const float* __restrict__ in,
                 const float* __restrict__ alphas,
                 float* __restrict__ out) {
    __shared__ float s_in[ICG][HALO][SINX];                    // 21888 B
    __shared__ __align__(16) float s_h[2][3][HALO][SHX];       // 34560 B
    __shared__ float s_a[6 * ICG * OCG];                       // 768 B
    __shared__ __align__(16) u64 s_d[3][8];                    // 192 B

    int bx = blockIdx.x, by = blockIdx.y;
    int n = blockIdx.z / GROUPS;
    int g = blockIdx.z % GROUPS;
    int tid = threadIdx.x;

    if (tid < 192) s_a[tid] = alphas[g * 192 + tid];
    if (tid >= 192 && tid < 192 + 15) {
        int t = tid - 192;
        s_d[t / 5][t % 5] = g_d2[g][t / 5][t % 5];
    }

    // haloed input tile (4 x 36 x 36 values, row stride SINX)
    int y0 = by * TILE - PAD, x0 = bx * TILE - PAD;
    const float* inb = in + ((size_t)n * (GROUPS * ICG) + g * ICG) * (HH * WW);
    for (int i = tid; i < ICG * HALO * HALO; i += 256) {
        int ic  = i / (HALO * HALO);
        int rem = i % (HALO * HALO);
        int yy  = rem / HALO, xx = rem % HALO;
        int gy = y0 + yy, gx = x0 + xx;
        float v = 0.f;
        if (gy >= 0 && gy < HH && gx >= 0 && gx < WW)
            v = inb[(size_t)ic * HH * WW + (size_t)gy * WW + gx];
        s_in[ic][yy][xx] = v;
    }
    __syncthreads();

    int pc = tid & 15;        // pair-col 0..15
    int rp = tid >> 4;        // row-pair 0..15
    int r  = rp * 2;
    int c  = pc * 2;

    // acc[ocp*4 + px]; px: 0=(r,c) 1=(r,c+1) 2=(r+1,c) 3=(r+1,c+1)
    u64 acc[16];
#pragma unroll
    for (int k = 0; k < 16; k++) acc[k] = 0ull;

    for (int icp = 0; icp < 2; icp++) {
        if (icp) __syncthreads();   // prior s_h fully consumed

        // ---- coop horizontal: 2 ics x 36 rows x 4 chunks of 8 x ----
        for (int s = tid; s < 288; s += 256) {
            int ic2 = s / 144;
            int rem = s - ic2 * 144;
            int y   = rem >> 2;
            int ch  = rem & 3;
            const float* base = &s_in[icp * 2 + ic2][y][ch * 8];

            u64 A[6]; float2 F[6];
#pragma unroll
            for (int k = 0; k < 6; k++) {
                A[k] = *(const u64*)(base + 2 * k);
                F[k] = uview(A[k]);
            }
            u64 S[5];
#pragma unroll
            for (int k = 0; k < 5; k++) S[k] = pk2f(F[k].y, F[k + 1].x);

            float* hrow = &s_h[ic2][0][y][ch * 8];
#pragma unroll
            for (int j = 0; j < 3; j++) {
                ulonglong2 da = *(const ulonglong2*)&s_d[j][0];
                ulonglong2 db = *(const ulonglong2*)&s_d[j][2];
                u64 d4 = s_d[j][4];
                u64 O[4];
#pragma unroll
                for (int k = 0; k < 4; k++) {
                    u64 o = 0ull;
                    o = fma2(A[k],     da.x, o);
                    o = fma2(S[k],     da.y, o);
                    o = fma2(A[k + 1], db.x, o);
                    o = fma2(S[k + 1], db.y, o);
                    o = fma2(A[k + 2], d4,   o);
                    O[k] = o;
                }
                ulonglong2* st = (ulonglong2*)(hrow + j * (HALO * SHX));
                st[0] = make_ulonglong2(O[0], O[1]);
                st[1] = make_ulonglong2(O[2], O[3]);
            }
        }
        __syncthreads();

        // ---- per-thread: vertical + pointwise ----
#pragma unroll
        for (int ic2 = 0; ic2 < 2; ic2++) {
            int ic = icp * 2 + ic2;
#pragma unroll
            for (int j = 0; j < 3; j++) {
                const float* hb = &s_h[ic2][j][r][c];
                u64 rows[6];
#pragma unroll
                for (int k = 0; k < 6; k++)
                    rows[k] = *(const u64*)(hb + k * SHX);
#pragma unroll
                for (int i = 0; i <= 2 - j; i++) {
                    // dd loaded per combo (broadcast LDS, N=1) — saves 10 regs
                    u64 dd[5];
                    {
                        ulonglong2 da = *(const ulonglong2*)&s_d[i][0];
                        ulonglong2 db = *(const ulonglong2*)&s_d[i][2];
                        dd[0] = da.x; dd[1] = da.y;
                        dd[2] = db.x; dd[3] = db.y;
                        dd[4] = s_d[i][4];
                    }
                    u64 m0 = 0ull, m1 = 0ull;
#pragma unroll
                    for (int k = 0; k < 5; k++) {
                        m0 = fma2(rows[k],     dd[k], m0);
                        m1 = fma2(rows[k + 1], dd[k], m1);
                    }
                    float2 f0 = uview(m0), f1 = uview(m1);
                    u64 h[4] = {dup2(f0.x), dup2(f0.y),
                                dup2(f1.x), dup2(f1.y)};
                    int ij = (i == 0) ? j : ((i == 1) ? 3 + j : 5);
                    const ulonglong2* ap =
                        (const ulonglong2*)&s_a[(ij * ICG + ic) * OCG];
                    ulonglong2 aA = ap[0];
                    ulonglong2 aB = ap[1];
#pragma unroll
                    for (int px = 0; px < 4; px++) {
                        acc[0 * 4 + px] = fma2(h[px], aA.x, acc[0 * 4 + px]);
                        acc[1 * 4 + px] = fma2(h[px], aA.y, acc[1 * 4 + px]);
                        acc[2 * 4 + px] = fma2(h[px], aB.x, acc[2 * 4 + px]);
                        acc[3 * 4 + px] = fma2(h[px], aB.y, acc[3 * 4 + px]);
                    }
                }
            }
        }
    }

    // ---- epilogue: transpose oc-pairs -> col-pairs, 16 STG.64 ----
    int gy = by * TILE + r, gx = bx * TILE + c;
    float* ob = out + (((size_t)n * (GROUPS * OCG) + g * OCG) * HH + gy) * (size_t)WW + gx;
#pragma unroll
    for (int ocp = 0; ocp < 4; ocp++) {
#pragma unroll
        for (int row = 0; row < 2; row++) {
            float2 va = uview(acc[ocp * 4 + row * 2 + 0]);
            float2 vb = uview(acc[ocp * 4 + row * 2 + 1]);
            u64 lo = pk2f(va.x, vb.x);
            u64 hi = pk2f(va.y, vb.y);
            *(u64*)(ob + (size_t)(2 * ocp)     * HH * WW + row * WW) = lo;
            *(u64*)(ob + (size_t)(2 * ocp + 1) * HH * WW + row * WW) = hi;
        }
    }
}

// ---------------------------------------------------------------------------
extern "C" void kernel_launch(void* const* d_in, const int* in_sizes, int n_in,
                              void* d_out, int out_size) {
    const float* data   = (const float*)d_in[0];  // [16,20,384,384]
    const float* alphas = (const float*)d_in[1];  // [5,6,4,8]
    const float* scales = (const float*)d_in[2];  // [5]
    float* out = (float*)d_out;                   // [16,40,384,384]

    make_filters_kernel<<<1, 32>>>(scales);

    dim3 grid(WW / TILE, HH / TILE, NBATCH * GROUPS);  // 12 x 12 x 80
    conv_kernel<<<grid, 256>>>(data, alphas, out);
}